// round 1
// baseline (speedup 1.0000x reference)
#include <cuda_runtime.h>
#include <math.h>

// ---------------- problem constants ----------------
#define S_LEN   32
#define T_LEN   32
#define BATCH   512
#define HID     1024
#define EMB     256
#define ADIM    1024
#define VSRC    64
#define VTGT    70
#define START_TOK 1
#define G3H     (3*HID)

// ---------------- scratch (static __device__ — no allocation) ----------------
__device__ float g_Menc[VSRC*G3H];            // emb_src @ W_ih_enc.T + b_ih_enc
__device__ float g_Mtgt[VTGT*G3H];            // emb_tgt @ W_ih_dec[:,H:].T + b_ih_dec
__device__ float g_h[BATCH*HID];              // current hidden state
__device__ float g_encops[S_LEN*BATCH*HID];   // encoder outputs (64 MB)
__device__ float g_encpart[S_LEN*BATCH*ADIM]; // enc_ops @ W_attn[H:] + b_attn (64 MB)
__device__ float g_gh[BATCH*G3H];             // h @ W_hh.T + b_hh
__device__ float g_gi[BATCH*G3H];             // ctx @ W_ih_dec[:,:H].T
__device__ float g_hW[BATCH*ADIM];            // h @ W_attn[:H]
__device__ float g_scores[S_LEN*BATCH];
__device__ float g_ctx[BATCH*HID];
__device__ int   g_x[BATCH];                  // current decoder input token

// ---------------- SGEMM: C[M,N] = A[M,K] * B (+bias[n]) ----------------
// BT=true : B is (N,K) row-major with leading dim ldb  (i.e. C = A @ B^T)
// BT=false: B is (K,N) row-major with leading dim ldb  (i.e. C = A @ B)
// Tile: BM=128, BN=64, BK=16, 256 threads, 8x4 per thread.
// All M,N,K used here are exact multiples of the tile dims (no guards).
template<bool BT>
__global__ __launch_bounds__(256)
void sgemm(const float* __restrict__ A, int lda,
           const float* __restrict__ B, int ldb,
           float* __restrict__ C, int ldc,
           int K, const float* __restrict__ bias)
{
    __shared__ float As[16][128];
    __shared__ float Bs[16][64];
    const int t   = threadIdx.x;
    const int bm0 = blockIdx.y * 128;
    const int bn0 = blockIdx.x * 64;
    const int tx  = t & 15;        // 0..15 -> n groups of 4
    const int ty  = t >> 4;        // 0..15 -> m groups of 8
    const int ar  = t >> 2;        // 0..63
    const int ac  = (t & 3) * 4;   // 0,4,8,12
    const int kr  = t >> 4;        // 0..15 (NN B load)
    const int nc4 = (t & 15) * 4;  // 0..60 (NN B load)

    float acc[8][4];
#pragma unroll
    for (int i = 0; i < 8; ++i)
#pragma unroll
        for (int j = 0; j < 4; ++j) acc[i][j] = 0.f;

    for (int k0 = 0; k0 < K; k0 += 16) {
        // load A tile (128 x 16), store transposed As[k][m]
#pragma unroll
        for (int r = 0; r < 2; ++r) {
            int m = ar + 64 * r;
            float4 v = *(const float4*)(A + (size_t)(bm0 + m) * lda + k0 + ac);
            As[ac + 0][m] = v.x; As[ac + 1][m] = v.y;
            As[ac + 2][m] = v.z; As[ac + 3][m] = v.w;
        }
        if (BT) {
            float4 v = *(const float4*)(B + (size_t)(bn0 + ar) * ldb + k0 + ac);
            Bs[ac + 0][ar] = v.x; Bs[ac + 1][ar] = v.y;
            Bs[ac + 2][ar] = v.z; Bs[ac + 3][ar] = v.w;
        } else {
            float4 v = *(const float4*)(B + (size_t)(k0 + kr) * ldb + bn0 + nc4);
            *(float4*)&Bs[kr][nc4] = v;
        }
        __syncthreads();
#pragma unroll
        for (int kk = 0; kk < 16; ++kk) {
            float a[8], bb[4];
#pragma unroll
            for (int i = 0; i < 8; ++i) a[i] = As[kk][ty * 8 + i];
#pragma unroll
            for (int j = 0; j < 4; ++j) bb[j] = Bs[kk][tx * 4 + j];
#pragma unroll
            for (int i = 0; i < 8; ++i)
#pragma unroll
                for (int j = 0; j < 4; ++j)
                    acc[i][j] = fmaf(a[i], bb[j], acc[i][j]);
        }
        __syncthreads();
    }
#pragma unroll
    for (int i = 0; i < 8; ++i) {
        int m = bm0 + ty * 8 + i;
#pragma unroll
        for (int j = 0; j < 4; ++j) {
            int n = bn0 + tx * 4 + j;
            float v = acc[i][j];
            if (bias) v += bias[n];
            C[(size_t)m * ldc + n] = v;
        }
    }
}

// ---------------- tiny precompute: out[i][g] = bias[g] + emb[i,:] . W[g, off:off+E] ----
__global__ void emb_gemm(const float* __restrict__ emb, const float* __restrict__ W,
                         const float* __restrict__ bias, float* __restrict__ out,
                         int rows, int ldw, int off)
{
    int idx = blockIdx.x * blockDim.x + threadIdx.x;
    if (idx >= rows * G3H) return;
    int i = idx / G3H, g = idx % G3H;
    const float* er = emb + (size_t)i * EMB;
    const float* wr = W + (size_t)g * ldw + off;
    float acc = bias[g];
#pragma unroll 8
    for (int e = 0; e < EMB; ++e) acc = fmaf(er[e], wr[e], acc);
    out[idx] = acc;
}

__device__ __forceinline__ float sigm(float x) { return 1.f / (1.f + expf(-x)); }

// ---------------- GRU gate kernels ----------------
__global__ void enc_gates(const int* __restrict__ src, int s)
{
    int idx = blockIdx.x * 256 + threadIdx.x;   // BATCH*HID threads
    int b = idx >> 10, j = idx & 1023;
    int id = src[s * BATCH + b];
    const float* mi = g_Menc + (size_t)id * G3H;   // gi (+b_ih folded)
    const float* gh = g_gh   + (size_t)b  * G3H;   // gh (+b_hh folded via sgemm bias)
    float r = sigm(mi[j]           + gh[j]);
    float z = sigm(mi[HID + j]     + gh[HID + j]);
    float n = tanhf(mi[2*HID + j]  + r * gh[2*HID + j]);
    float hold = g_h[idx];
    float hn = (1.f - z) * n + z * hold;
    g_h[idx] = hn;
    g_encops[(size_t)s * BATCH * HID + idx] = hn;
}

__global__ void dec_gates()
{
    int idx = blockIdx.x * 256 + threadIdx.x;
    int b = idx >> 10, j = idx & 1023;
    int id = g_x[b];
    const float* mi = g_Mtgt + (size_t)id * G3H;   // emb part of gi (+b_ih folded)
    const float* gi = g_gi   + (size_t)b  * G3H;   // ctx part of gi
    const float* gh = g_gh   + (size_t)b  * G3H;   // gh (+b_hh folded)
    float r = sigm(mi[j]          + gi[j]          + gh[j]);
    float z = sigm(mi[HID + j]    + gi[HID + j]    + gh[HID + j]);
    float n = tanhf(mi[2*HID + j] + gi[2*HID + j]  + r * gh[2*HID + j]);
    float hold = g_h[idx];
    g_h[idx] = (1.f - z) * n + z * hold;
}

// ---------------- attention: scores[s,b] = v . tanh(enc_part[s,b,:] + hW[b,:]) ----------
__global__ void attn_scores(const float* __restrict__ v_attn)
{
    int b = blockIdx.x, s = blockIdx.y, t = threadIdx.x; // 128 threads
    const float* ep = g_encpart + ((size_t)s * BATCH + b) * ADIM;
    const float* hw = g_hW + (size_t)b * ADIM;
    float p = 0.f;
#pragma unroll
    for (int a = t; a < ADIM; a += 128)
        p = fmaf(v_attn[a], tanhf(ep[a] + hw[a]), p);
#pragma unroll
    for (int o = 16; o; o >>= 1) p += __shfl_xor_sync(0xffffffffu, p, o);
    __shared__ float ws[4];
    if ((t & 31) == 0) ws[t >> 5] = p;
    __syncthreads();
    if (t == 0) g_scores[s * BATCH + b] = ws[0] + ws[1] + ws[2] + ws[3];
}

// ---------------- softmax over s + context + attn output ----------------
__global__ void softmax_ctx(float* __restrict__ attn_row)   // attn_row: (B, S) for this step
{
    int b = blockIdx.x, t = threadIdx.x;  // 256 threads
    __shared__ float al[S_LEN];
    if (t < 32) {
        float sc = g_scores[t * BATCH + b];
        float m = sc;
#pragma unroll
        for (int o = 16; o; o >>= 1) m = fmaxf(m, __shfl_xor_sync(0xffffffffu, m, o));
        float e = expf(sc - m);
        float sm = e;
#pragma unroll
        for (int o = 16; o; o >>= 1) sm += __shfl_xor_sync(0xffffffffu, sm, o);
        float a = e / sm;
        al[t] = a;
        attn_row[(size_t)b * S_LEN + t] = a;
    }
    __syncthreads();
    for (int h = t; h < HID; h += 256) {
        float acc = 0.f;
#pragma unroll
        for (int s2 = 0; s2 < S_LEN; ++s2)
            acc = fmaf(al[s2], g_encops[((size_t)s2 * BATCH + b) * HID + h], acc);
        g_ctx[(size_t)b * HID + h] = acc;
    }
}

// ---------------- output projection + next-token selection ----------------
__global__ void out_step(const float* __restrict__ W_out, const float* __restrict__ b_out,
                         const int* __restrict__ tgt, const int* __restrict__ tfp,
                         float* __restrict__ out_t, int t)
{
    int b = blockIdx.x, tid = threadIdx.x; // 128 threads
    __shared__ float hs[HID];
    __shared__ float vals[VTGT];
    for (int k = tid; k < HID; k += 128) hs[k] = g_h[(size_t)b * HID + k];
    __syncthreads();
    if (tid < VTGT) {
        float acc = b_out[tid];
#pragma unroll 8
        for (int k = 0; k < HID; ++k)
            acc = fmaf(hs[k], W_out[(size_t)k * VTGT + tid], acc);
        out_t[(size_t)b * VTGT + tid] = acc;
        vals[tid] = acc;
    }
    __syncthreads();
    if (tid == 0) {
        int nx;
        if (tfp[0]) nx = tgt[t * BATCH + b];
        else {
            float bm = vals[0]; nx = 0;
            for (int v = 1; v < VTGT; ++v) if (vals[v] > bm) { bm = vals[v]; nx = v; }
        }
        g_x[b] = nx;
    }
}

// ---------------- small init kernels ----------------
__global__ void zero_h() { g_h[blockIdx.x * 256 + threadIdx.x] = 0.f; }
__global__ void init_x(const int* __restrict__ tgt)
{
    int b = blockIdx.x * 64 + threadIdx.x;
    if (b < BATCH) g_x[b] = tgt[b];       // target[0]
}
__global__ void row0(float* __restrict__ out0)
{
    int idx = blockIdx.x * 256 + threadIdx.x;
    if (idx < BATCH * VTGT) out0[idx] = ((idx % VTGT) == START_TOK) ? 1.f : 0.f;
}

// ---------------- host launcher (graph-capturable: kernels only) ----------------
extern "C" void kernel_launch(void* const* d_in, const int* in_sizes, int n_in,
                              void* d_out, int out_size)
{
    const int*   src      = (const int*)  d_in[0];
    const int*   tgt      = (const int*)  d_in[1];
    const int*   tf       = (const int*)  d_in[2];
    const float* emb_src  = (const float*)d_in[3];
    const float* W_ih_enc = (const float*)d_in[4];
    const float* W_hh_enc = (const float*)d_in[5];
    const float* b_ih_enc = (const float*)d_in[6];
    const float* b_hh_enc = (const float*)d_in[7];
    const float* emb_tgt  = (const float*)d_in[8];
    const float* W_attn   = (const float*)d_in[9];
    const float* b_attn   = (const float*)d_in[10];
    const float* v_attn   = (const float*)d_in[11];
    const float* W_ih_dec = (const float*)d_in[12];
    const float* W_hh_dec = (const float*)d_in[13];
    const float* b_ih_dec = (const float*)d_in[14];
    const float* b_hh_dec = (const float*)d_in[15];
    const float* W_out    = (const float*)d_in[16];
    const float* b_out    = (const float*)d_in[17];

    float* outp  = (float*)d_out;
    float* attnp = outp + (size_t)T_LEN * BATCH * VTGT;

    // scratch device pointers (host-side symbol query; no allocation)
    void *pMenc, *pMtgt, *ph, *pencops, *pencpart, *pgh, *pgi, *phW, *pctx;
    cudaGetSymbolAddress(&pMenc,     g_Menc);
    cudaGetSymbolAddress(&pMtgt,     g_Mtgt);
    cudaGetSymbolAddress(&ph,        g_h);
    cudaGetSymbolAddress(&pencops,   g_encops);
    cudaGetSymbolAddress(&pencpart,  g_encpart);
    cudaGetSymbolAddress(&pgh,       g_gh);
    cudaGetSymbolAddress(&pgi,       g_gi);
    cudaGetSymbolAddress(&phW,       g_hW);
    cudaGetSymbolAddress(&pctx,      g_ctx);

    // ---- precompute embedding GEMMs (biases folded) ----
    emb_gemm<<<(VSRC * G3H + 255) / 256, 256>>>(emb_src, W_ih_enc, b_ih_enc,
                                                (float*)pMenc, VSRC, EMB, 0);
    emb_gemm<<<(VTGT * G3H + 255) / 256, 256>>>(emb_tgt, W_ih_dec, b_ih_dec,
                                                (float*)pMtgt, VTGT, HID + EMB, HID);
    zero_h<<<BATCH * HID / 256, 256>>>();
    init_x<<<(BATCH + 63) / 64, 64>>>(tgt);
    row0<<<(BATCH * VTGT + 255) / 256, 256>>>(outp);

    // ---- encoder: 32 sequential GRU steps ----
    dim3 gEnc(G3H / 64, BATCH / 128);   // (48, 4)
    for (int s = 0; s < S_LEN; ++s) {
        sgemm<true><<<gEnc, 256>>>((const float*)ph, HID, W_hh_enc, HID,
                                   (float*)pgh, G3H, HID, b_hh_enc);
        enc_gates<<<BATCH * HID / 256, 256>>>(src, s);
    }

    // ---- attention precompute: enc_part = enc_ops @ W_attn[H:] + b_attn ----
    dim3 gEP(ADIM / 64, (S_LEN * BATCH) / 128);  // (16, 128)
    sgemm<false><<<gEP, 256>>>((const float*)pencops, HID, W_attn + (size_t)HID * ADIM,
                               ADIM, (float*)pencpart, ADIM, HID, b_attn);

    // ---- decoder: 31 sequential steps ----
    dim3 gHW(ADIM / 64, BATCH / 128);   // (16, 4)
    dim3 gDec(G3H / 64, BATCH / 128);   // (48, 4)
    for (int t = 1; t < T_LEN; ++t) {
        // h_part = h @ W_attn[:H]
        sgemm<false><<<gHW, 256>>>((const float*)ph, HID, W_attn, ADIM,
                                   (float*)phW, ADIM, HID, nullptr);
        attn_scores<<<dim3(BATCH, S_LEN), 128>>>(v_attn);
        softmax_ctx<<<BATCH, 256>>>(attnp + (size_t)(t - 1) * BATCH * S_LEN);
        // gi(ctx part) = ctx @ W_ih_dec[:, :H].T
        sgemm<true><<<gDec, 256>>>((const float*)pctx, HID, W_ih_dec, HID + EMB,
                                   (float*)pgi, G3H, HID, nullptr);
        // gh = h @ W_hh_dec.T + b_hh_dec
        sgemm<true><<<gDec, 256>>>((const float*)ph, HID, W_hh_dec, HID,
                                   (float*)pgh, G3H, HID, b_hh_dec);
        dec_gates<<<BATCH * HID / 256, 256>>>();
        out_step<<<BATCH, 128>>>(W_out, b_out, tgt, tf,
                                 outp + (size_t)t * BATCH * VTGT, t);
    }
}

// round 2
// speedup vs baseline: 2.0808x; 2.0808x over previous
#include <cuda_runtime.h>
#include <math.h>

// ---------------- problem constants ----------------
#define S_LEN   32
#define T_LEN   32
#define BATCH   512
#define HID     1024
#define EMB     256
#define ADIM    1024
#define VSRC    64
#define VTGT    70
#define START_TOK 1
#define G3H     (3*HID)
#define NCOMB   4096          // [hW (1024) | gh_r | gh_z | gh_n]

// ---------------- scratch (static __device__ — no allocation) ----------------
__device__ float g_Menc[VSRC*G3H];            // emb_src @ W_ih_enc.T + b_ih_enc
__device__ float g_Mtgt[VTGT*G3H];            // emb_tgt @ W_ih_dec[:,H:].T + b_ih_dec
__device__ float g_h[BATCH*HID];              // current hidden state
__device__ float g_encops[S_LEN*BATCH*HID];   // encoder outputs
__device__ float g_encpart[S_LEN*BATCH*ADIM]; // enc_ops @ W_attn[H:] + b_attn
__device__ float g_gh[BATCH*G3H];             // encoder: h @ W_hh_enc.T + b_hh
__device__ float g_gi[BATCH*G3H];             // decoder: ctx @ W_ih_dec[:,:H].T
__device__ float g_hWgh[BATCH*NCOMB];         // decoder: h @ [W_attn[:H] | W_hh_dec^T]
__device__ float g_ctx[BATCH*HID];
__device__ int   g_x[BATCH];
// pre-transposed / tf32-rounded weights
__device__ float g_Whe[HID*G3H];              // W_hh_enc^T           [K=H][N=3H]
__device__ float g_Wid[HID*G3H];              // W_ih_dec[:, :H]^T    [K=H][N=3H]
__device__ float g_Wcomb[HID*NCOMB];          // [W_attn[:H] | W_hh_dec^T]
__device__ float g_Wap[HID*ADIM];             // W_attn[H:]  (rounded)
__device__ float g_bcomb[NCOMB];

// ---------------- tf32 helpers ----------------
__device__ __forceinline__ unsigned f2tf(float f) {
    unsigned u; asm("cvt.rna.tf32.f32 %0, %1;" : "=r"(u) : "f"(f)); return u;
}
__device__ __forceinline__ float f2tf_f(float f) { return __uint_as_float(f2tf(f)); }

__device__ __forceinline__ void mma8(float* c, const unsigned* a, const unsigned* b) {
    asm volatile("mma.sync.aligned.m16n8k8.row.col.f32.tf32.tf32.f32 "
        "{%0,%1,%2,%3}, {%4,%5,%6,%7}, {%8,%9}, {%0,%1,%2,%3};"
        : "+f"(c[0]), "+f"(c[1]), "+f"(c[2]), "+f"(c[3])
        : "r"(a[0]), "r"(a[1]), "r"(a[2]), "r"(a[3]), "r"(b[0]), "r"(b[1]));
}

// ---------------- tf32 tensor-core GEMM (NN): C[M,N] = A[M,K] @ B[K,N] (+bias) ----
// A: fp32 (converted to tf32 on SMEM stage). B: pre-rounded tf32 (stored as float).
// BM=128, BN=64, BK=32, 256 threads (8 warps, 4x2), warp tile 32x32.
__global__ __launch_bounds__(256)
void gemm_tf32(const float* __restrict__ A, int lda,
               const float* __restrict__ B, int ldb,
               float* __restrict__ C, int ldc,
               int K, const float* __restrict__ bias)
{
    __shared__ unsigned As[32][128 + 8];   // [k][m], pad 8 -> conflict-free frag loads
    __shared__ unsigned Bs[32][64 + 8];    // [k][n]
    const int tid  = threadIdx.x;
    const int wid  = tid >> 5, lane = tid & 31;
    const int wm   = wid & 3, wn = wid >> 2;        // warp tile origin (wm*32, wn*32)
    const int g    = lane >> 2, t4 = lane & 3;
    const int m0   = blockIdx.y * 128;
    const int n0   = blockIdx.x * 64;
    const int arow = tid >> 1, acol = (tid & 1) * 16;
    const int brow = tid >> 4, bcol = (tid & 15) * 4;

    float acc[2][4][4];
#pragma unroll
    for (int i = 0; i < 2; ++i)
#pragma unroll
        for (int j = 0; j < 4; ++j)
#pragma unroll
            for (int q = 0; q < 4; ++q) acc[i][j][q] = 0.f;

    for (int k0 = 0; k0 < K; k0 += 32) {
        // stage A (128x32), transpose + round-to-tf32
#pragma unroll
        for (int i = 0; i < 4; ++i) {
            float4 v = *(const float4*)(A + (size_t)(m0 + arow) * lda + k0 + acol + 4*i);
            As[acol + 4*i + 0][arow] = f2tf(v.x);
            As[acol + 4*i + 1][arow] = f2tf(v.y);
            As[acol + 4*i + 2][arow] = f2tf(v.z);
            As[acol + 4*i + 3][arow] = f2tf(v.w);
        }
        // stage B (32x64), already tf32 bits
#pragma unroll
        for (int i = 0; i < 2; ++i) {
            float4 v = *(const float4*)(B + (size_t)(k0 + brow + 16*i) * ldb + n0 + bcol);
            uint4 u = make_uint4(__float_as_uint(v.x), __float_as_uint(v.y),
                                 __float_as_uint(v.z), __float_as_uint(v.w));
            *(uint4*)&Bs[brow + 16*i][bcol] = u;
        }
        __syncthreads();
#pragma unroll
        for (int kk = 0; kk < 32; kk += 8) {
            unsigned a[2][4], b[4][2];
#pragma unroll
            for (int i = 0; i < 2; ++i) {
                int m = wm * 32 + i * 16 + g;
                a[i][0] = As[kk + t4][m];
                a[i][1] = As[kk + t4][m + 8];
                a[i][2] = As[kk + t4 + 4][m];
                a[i][3] = As[kk + t4 + 4][m + 8];
            }
#pragma unroll
            for (int j = 0; j < 4; ++j) {
                int n = wn * 32 + j * 8 + g;
                b[j][0] = Bs[kk + t4][n];
                b[j][1] = Bs[kk + t4 + 4][n];
            }
#pragma unroll
            for (int i = 0; i < 2; ++i)
#pragma unroll
                for (int j = 0; j < 4; ++j)
                    mma8(acc[i][j], a[i], b[j]);
        }
        __syncthreads();
    }
    // epilogue
#pragma unroll
    for (int i = 0; i < 2; ++i) {
        int m = m0 + wm * 32 + i * 16 + g;
#pragma unroll
        for (int j = 0; j < 4; ++j) {
            int n = n0 + wn * 32 + j * 8 + 2 * t4;
            float b0 = bias ? bias[n] : 0.f;
            float b1 = bias ? bias[n + 1] : 0.f;
            *(float2*)(C + (size_t)m * ldc + n) =
                make_float2(acc[i][j][0] + b0, acc[i][j][1] + b1);
            *(float2*)(C + (size_t)(m + 8) * ldc + n) =
                make_float2(acc[i][j][2] + b0, acc[i][j][3] + b1);
        }
    }
}

// ---------------- weight prep (transpose + tf32 round) ----------------
__global__ void prep_whe(const float* __restrict__ W) {       // (3H,H) -> [k][n]
    int idx = blockIdx.x * 256 + threadIdx.x;
    if (idx >= HID * G3H) return;
    int k = idx / G3H, n = idx % G3H;
    g_Whe[idx] = f2tf_f(W[(size_t)n * HID + k]);
}
__global__ void prep_wid(const float* __restrict__ W) {       // W_ih_dec[:, :H]^T
    int idx = blockIdx.x * 256 + threadIdx.x;
    if (idx >= HID * G3H) return;
    int k = idx / G3H, n = idx % G3H;
    g_Wid[idx] = f2tf_f(W[(size_t)n * (HID + EMB) + k]);
}
__global__ void prep_wcomb(const float* __restrict__ Wattn, const float* __restrict__ Whd,
                           const float* __restrict__ bhh) {
    int idx = blockIdx.x * 256 + threadIdx.x;
    if (idx >= HID * NCOMB) return;
    int k = idx / NCOMB, n = idx % NCOMB;
    float v = (n < ADIM) ? Wattn[(size_t)k * ADIM + n]
                         : Whd[(size_t)(n - ADIM) * HID + k];
    g_Wcomb[idx] = f2tf_f(v);
    if (idx < NCOMB) g_bcomb[idx] = (idx < ADIM) ? 0.f : bhh[idx - ADIM];
}
__global__ void prep_wap(const float* __restrict__ Wattn) {   // rows H..2H-1
    int idx = blockIdx.x * 256 + threadIdx.x;
    if (idx >= HID * ADIM) return;
    g_Wap[idx] = f2tf_f(Wattn[(size_t)HID * ADIM + idx]);
}

// ---------------- embedding precompute (biases folded) ----------------
__global__ void emb_gemm(const float* __restrict__ emb, const float* __restrict__ W,
                         const float* __restrict__ bias, float* __restrict__ out,
                         int rows, int ldw, int off)
{
    int idx = blockIdx.x * blockDim.x + threadIdx.x;
    if (idx >= rows * G3H) return;
    int i = idx / G3H, gg = idx % G3H;
    const float* er = emb + (size_t)i * EMB;
    const float* wr = W + (size_t)gg * ldw + off;
    float acc = bias[gg];
#pragma unroll 8
    for (int e = 0; e < EMB; ++e) acc = fmaf(er[e], wr[e], acc);
    out[idx] = acc;
}

__device__ __forceinline__ float sigm(float x) { return 1.f / (1.f + expf(-x)); }

// ---------------- GRU gate kernels ----------------
__global__ void enc_gates(const int* __restrict__ src, int s)
{
    int idx = blockIdx.x * 256 + threadIdx.x;
    int b = idx >> 10, j = idx & 1023;
    int id = src[s * BATCH + b];
    const float* mi = g_Menc + (size_t)id * G3H;
    const float* gh = g_gh   + (size_t)b  * G3H;
    float r = sigm(mi[j]          + gh[j]);
    float z = sigm(mi[HID + j]    + gh[HID + j]);
    float n = tanhf(mi[2*HID + j] + r * gh[2*HID + j]);
    float hold = g_h[idx];
    float hn = (1.f - z) * n + z * hold;
    g_h[idx] = hn;
    g_encops[(size_t)s * BATCH * HID + idx] = hn;
}

__global__ void dec_gates()
{
    int idx = blockIdx.x * 256 + threadIdx.x;
    int b = idx >> 10, j = idx & 1023;
    int id = g_x[b];
    const float* mi = g_Mtgt + (size_t)id * G3H;
    const float* gi = g_gi   + (size_t)b  * G3H;
    const float* gh = g_hWgh + (size_t)b  * NCOMB + ADIM;   // [r|z|n] at cols 1024..
    float r = sigm(mi[j]          + gi[j]          + gh[j]);
    float z = sigm(mi[HID + j]    + gi[HID + j]    + gh[HID + j]);
    float n = tanhf(mi[2*HID + j] + gi[2*HID + j]  + r * gh[2*HID + j]);
    float hold = g_h[idx];
    g_h[idx] = (1.f - z) * n + z * hold;
}

// ---------------- fused attention: scores -> softmax -> ctx -> attn out ----------
__global__ __launch_bounds__(256)
void attn_fused(const float* __restrict__ v_attn, float* __restrict__ attn_row)
{
    int b = blockIdx.x, tid = threadIdx.x;
    int w = tid >> 5, lane = tid & 31;
    __shared__ float sc[S_LEN];
    __shared__ float al[S_LEN];
    const float* hw = g_hWgh + (size_t)b * NCOMB;           // cols 0..1023
#pragma unroll
    for (int i = 0; i < 4; ++i) {
        int s = w + 8 * i;
        const float* ep = g_encpart + ((size_t)s * BATCH + b) * ADIM;
        float p = 0.f;
#pragma unroll 4
        for (int a = lane; a < ADIM; a += 32)
            p = fmaf(v_attn[a], tanhf(ep[a] + hw[a]), p);
#pragma unroll
        for (int o = 16; o; o >>= 1) p += __shfl_xor_sync(0xffffffffu, p, o);
        if (lane == 0) sc[s] = p;
    }
    __syncthreads();
    if (tid < 32) {
        float x = sc[tid];
        float m = x;
#pragma unroll
        for (int o = 16; o; o >>= 1) m = fmaxf(m, __shfl_xor_sync(0xffffffffu, m, o));
        float e = expf(x - m);
        float smv = e;
#pragma unroll
        for (int o = 16; o; o >>= 1) smv += __shfl_xor_sync(0xffffffffu, smv, o);
        float a = e / smv;
        al[tid] = a;
        attn_row[(size_t)b * S_LEN + tid] = a;
    }
    __syncthreads();
    for (int h = tid; h < HID; h += 256) {
        float acc = 0.f;
#pragma unroll
        for (int s2 = 0; s2 < S_LEN; ++s2)
            acc = fmaf(al[s2], g_encops[((size_t)s2 * BATCH + b) * HID + h], acc);
        g_ctx[(size_t)b * HID + h] = acc;
    }
}

// ---------------- output projection + next-token selection ----------------
__global__ void out_step(const float* __restrict__ W_out, const float* __restrict__ b_out,
                         const int* __restrict__ tgt, const int* __restrict__ tfp,
                         float* __restrict__ out_t, int t)
{
    int b = blockIdx.x, tid = threadIdx.x; // 128 threads
    __shared__ float hs[HID];
    __shared__ float vals[VTGT];
    for (int k = tid; k < HID; k += 128) hs[k] = g_h[(size_t)b * HID + k];
    __syncthreads();
    if (tid < VTGT) {
        float a0 = b_out[tid], a1 = 0.f, a2 = 0.f, a3 = 0.f;
#pragma unroll 4
        for (int k = 0; k < HID; k += 4) {
            a0 = fmaf(hs[k+0], W_out[(size_t)(k+0) * VTGT + tid], a0);
            a1 = fmaf(hs[k+1], W_out[(size_t)(k+1) * VTGT + tid], a1);
            a2 = fmaf(hs[k+2], W_out[(size_t)(k+2) * VTGT + tid], a2);
            a3 = fmaf(hs[k+3], W_out[(size_t)(k+3) * VTGT + tid], a3);
        }
        float acc = (a0 + a1) + (a2 + a3);
        out_t[(size_t)b * VTGT + tid] = acc;
        vals[tid] = acc;
    }
    __syncthreads();
    if (tid == 0) {
        int nx;
        if (tfp[0]) nx = tgt[t * BATCH + b];
        else {
            float bm = vals[0]; nx = 0;
            for (int v = 1; v < VTGT; ++v) if (vals[v] > bm) { bm = vals[v]; nx = v; }
        }
        g_x[b] = nx;
    }
}

// ---------------- small init kernels ----------------
__global__ void zero_h() { g_h[blockIdx.x * 256 + threadIdx.x] = 0.f; }
__global__ void init_x(const int* __restrict__ tgt)
{
    int b = blockIdx.x * 64 + threadIdx.x;
    if (b < BATCH) g_x[b] = tgt[b];
}
__global__ void row0(float* __restrict__ out0)
{
    int idx = blockIdx.x * 256 + threadIdx.x;
    if (idx < BATCH * VTGT) out0[idx] = ((idx % VTGT) == START_TOK) ? 1.f : 0.f;
}

// ---------------- host launcher (graph-capturable: kernels only) ----------------
extern "C" void kernel_launch(void* const* d_in, const int* in_sizes, int n_in,
                              void* d_out, int out_size)
{
    const int*   src      = (const int*)  d_in[0];
    const int*   tgt      = (const int*)  d_in[1];
    const int*   tf       = (const int*)  d_in[2];
    const float* emb_src  = (const float*)d_in[3];
    const float* W_ih_enc = (const float*)d_in[4];
    const float* W_hh_enc = (const float*)d_in[5];
    const float* b_ih_enc = (const float*)d_in[6];
    const float* b_hh_enc = (const float*)d_in[7];
    const float* emb_tgt  = (const float*)d_in[8];
    const float* W_attn   = (const float*)d_in[9];
    const float* b_attn   = (const float*)d_in[10];
    const float* v_attn   = (const float*)d_in[11];
    const float* W_ih_dec = (const float*)d_in[12];
    const float* W_hh_dec = (const float*)d_in[13];
    const float* b_ih_dec = (const float*)d_in[14];
    const float* b_hh_dec = (const float*)d_in[15];
    const float* W_out    = (const float*)d_in[16];
    const float* b_out    = (const float*)d_in[17];

    float* outp  = (float*)d_out;
    float* attnp = outp + (size_t)T_LEN * BATCH * VTGT;

    void *pMenc, *pMtgt, *ph, *pencops, *pencpart, *pgh, *pgi, *phWgh, *pctx;
    void *pWhe, *pWid, *pWcomb, *pWap, *pbcomb;
    cudaGetSymbolAddress(&pMenc,    g_Menc);
    cudaGetSymbolAddress(&pMtgt,    g_Mtgt);
    cudaGetSymbolAddress(&ph,       g_h);
    cudaGetSymbolAddress(&pencops,  g_encops);
    cudaGetSymbolAddress(&pencpart, g_encpart);
    cudaGetSymbolAddress(&pgh,      g_gh);
    cudaGetSymbolAddress(&pgi,      g_gi);
    cudaGetSymbolAddress(&phWgh,    g_hWgh);
    cudaGetSymbolAddress(&pctx,     g_ctx);
    cudaGetSymbolAddress(&pWhe,     g_Whe);
    cudaGetSymbolAddress(&pWid,     g_Wid);
    cudaGetSymbolAddress(&pWcomb,   g_Wcomb);
    cudaGetSymbolAddress(&pWap,     g_Wap);
    cudaGetSymbolAddress(&pbcomb,   g_bcomb);

    // ---- weight prep (transpose + tf32 rounding) ----
    prep_whe  <<<(HID * G3H   + 255) / 256, 256>>>(W_hh_enc);
    prep_wid  <<<(HID * G3H   + 255) / 256, 256>>>(W_ih_dec);
    prep_wcomb<<<(HID * NCOMB + 255) / 256, 256>>>(W_attn, W_hh_dec, b_hh_dec);
    prep_wap  <<<(HID * ADIM  + 255) / 256, 256>>>(W_attn);

    // ---- embedding precompute ----
    emb_gemm<<<(VSRC * G3H + 255) / 256, 256>>>(emb_src, W_ih_enc, b_ih_enc,
                                                (float*)pMenc, VSRC, EMB, 0);
    emb_gemm<<<(VTGT * G3H + 255) / 256, 256>>>(emb_tgt, W_ih_dec, b_ih_dec,
                                                (float*)pMtgt, VTGT, HID + EMB, HID);
    zero_h<<<BATCH * HID / 256, 256>>>();
    init_x<<<(BATCH + 63) / 64, 64>>>(tgt);
    row0<<<(BATCH * VTGT + 255) / 256, 256>>>(outp);

    // ---- encoder: 32 sequential GRU steps ----
    dim3 gEnc(G3H / 64, BATCH / 128);    // (48, 4)
    for (int s = 0; s < S_LEN; ++s) {
        gemm_tf32<<<gEnc, 256>>>((const float*)ph, HID, (const float*)pWhe, G3H,
                                 (float*)pgh, G3H, HID, b_hh_enc);
        enc_gates<<<BATCH * HID / 256, 256>>>(src, s);
    }

    // ---- attention precompute: enc_part = enc_ops @ W_attn[H:] + b_attn ----
    dim3 gEP(ADIM / 64, (S_LEN * BATCH) / 128);   // (16, 128)
    gemm_tf32<<<gEP, 256>>>((const float*)pencops, HID, (const float*)pWap, ADIM,
                            (float*)pencpart, ADIM, HID, b_attn);

    // ---- decoder: 31 sequential steps ----
    dim3 gComb(NCOMB / 64, BATCH / 128); // (64, 4)
    dim3 gGi(G3H / 64, BATCH / 128);     // (48, 4)
    for (int t = 1; t < T_LEN; ++t) {
        // [hW | gh] = h @ [W_attn[:H] | W_hh_dec^T]   (single fused GEMM)
        gemm_tf32<<<gComb, 256>>>((const float*)ph, HID, (const float*)pWcomb, NCOMB,
                                  (float*)phWgh, NCOMB, HID, (const float*)pbcomb);
        attn_fused<<<BATCH, 256>>>(v_attn, attnp + (size_t)(t - 1) * BATCH * S_LEN);
        // gi(ctx part) = ctx @ W_ih_dec[:, :H].T
        gemm_tf32<<<gGi, 256>>>((const float*)pctx, HID, (const float*)pWid, G3H,
                                (float*)pgi, G3H, HID, nullptr);
        dec_gates<<<BATCH * HID / 256, 256>>>();
        out_step<<<BATCH, 128>>>(W_out, b_out, tgt, tf,
                                 outp + (size_t)t * BATCH * VTGT, t);
    }
}